// round 10
// baseline (speedup 1.0000x reference)
#include <cuda_runtime.h>
#include <stdint.h>

// CutoutColor: out[n,c,h,w] = colors[n,c] if h in [top, top+28) && w in [left, left+28)
//              else x[n,c,h,w]
// x [4096, 9, 84, 84] f32, colors [4096, 9] f32, tops/lefts [4096] i32.
//
// R9: 256-bit vectorization (sm_100+ ld/st.global.v8.b32). One thread = one
// 32B float8 vector across a channel GROUP (5 or 4 channels; 9 = 5+4 via
// grid.y) -> halves L1tex wavefronts per byte vs float4 (queue ~248
// entries/SM was overflowing at 40 warps x 9 LDG.128), doubling bytes in
// flight per queue slot. Vectors may straddle a row boundary (84 % 8 != 0):
// per-element mask from two row flags. Patch-interior full-skip + .cs kept.

#define N_      4096
#define C_      9
#define H_      84
#define W_      84
#define PATCH_  28
#define PLANE_  (H_ * W_)        // 7056 floats per (n,c) plane
#define PLANE8_ (PLANE_ / 8)     // 882 float8 vecs per plane

__device__ __forceinline__ void ldg256cs(const float* p, uint32_t r[8]) {
    asm volatile("ld.global.cs.v8.b32 {%0,%1,%2,%3,%4,%5,%6,%7}, [%8];"
                 : "=r"(r[0]), "=r"(r[1]), "=r"(r[2]), "=r"(r[3]),
                   "=r"(r[4]), "=r"(r[5]), "=r"(r[6]), "=r"(r[7])
                 : "l"(p));
}

__device__ __forceinline__ void stg256cs(float* p, const uint32_t r[8]) {
    asm volatile("st.global.cs.v8.b32 [%0], {%1,%2,%3,%4,%5,%6,%7,%8};"
                 :: "l"(p),
                    "r"(r[0]), "r"(r[1]), "r"(r[2]), "r"(r[3]),
                    "r"(r[4]), "r"(r[5]), "r"(r[6]), "r"(r[7])
                 : "memory");
}

template <int NCH>
__device__ __forceinline__ void process_group(const float* __restrict__ x,
                                              float*       __restrict__ out,
                                              const float* __restrict__ col,
                                              int base, unsigned m)
{
    if (m == 0xFFu) {
        // whole 32B vector inside the patch for every channel: pure writes
        #pragma unroll
        for (int c = 0; c < NCH; ++c) {
            uint32_t f = __float_as_uint(col[c]);
            uint32_t v[8] = {f, f, f, f, f, f, f, f};
            stg256cs(out + base + c * PLANE_, v);
        }
        return;
    }

    uint32_t v[NCH][8];
    #pragma unroll
    for (int c = 0; c < NCH; ++c)            // front-batched independent loads
        ldg256cs(x + base + c * PLANE_, v[c]);

    if (m) {
        #pragma unroll
        for (int c = 0; c < NCH; ++c) {
            const uint32_t f = __float_as_uint(col[c]);
            #pragma unroll
            for (int e = 0; e < 8; ++e)
                if ((m >> e) & 1u) v[c][e] = f;
        }
    }

    #pragma unroll
    for (int c = 0; c < NCH; ++c)
        stg256cs(out + base + c * PLANE_, v[c]);
}

__global__ __launch_bounds__(256)
void cutout_color_kernel(const float* __restrict__ x,
                         const float* __restrict__ colors,
                         const int*   __restrict__ tops,
                         const int*   __restrict__ lefts,
                         float*       __restrict__ out)
{
    const int t  = blockIdx.x * blockDim.x + threadIdx.x;  // 0 .. N*882-1, exact
    const int n  = t / PLANE8_;            // const-divisor -> mul/shift
    const int i8 = t - n * PLANE8_;        // float8 idx within plane, 0..881

    const int pos = i8 * 8;                // float idx within plane
    const int h0  = pos / W_;              // const-divisor -> mul/shift
    const int w0  = pos - h0 * W_;         // multiple of 4

    const int top  = tops[n];              // ~warp-uniform -> L1 broadcast
    const int left = lefts[n];
    const int lo = left, hi = left + PATCH_;

    const bool rin0 = (h0     >= top) & (h0     < top + PATCH_);
    const bool rin1 = (h0 + 1 >= top) & (h0 + 1 < top + PATCH_);

    // 8-bit element mask; vector may straddle one row boundary
    unsigned m = 0;
    #pragma unroll
    for (int e = 0; e < 8; ++e) {
        const int  we   = w0 + e;
        const bool over = we >= W_;
        const int  wc   = over ? we - W_ : we;
        const bool r    = over ? rin1 : rin0;
        if (r & (wc >= lo) & (wc < hi)) m |= (1u << e);
    }

    // float index of (n, c_group_base, pos); max ~260M < 2^31
    const int   nb  = n * (C_ * PLANE_);
    const float* col = colors + n * C_;

    if (blockIdx.y == 0)
        process_group<5>(x, out, col,           nb +            pos, m);
    else
        process_group<4>(x, out, col + 5,       nb + 5*PLANE_ + pos, m);
}

extern "C" void kernel_launch(void* const* d_in, const int* in_sizes, int n_in,
                              void* d_out, int out_size)
{
    const float* x      = (const float*)d_in[0];
    const float* colors = (const float*)d_in[1];
    const int*   tops   = (const int*)  d_in[2];
    const int*   lefts  = (const int*)  d_in[3];
    float*       out    = (float*)      d_out;

    dim3 block(256);
    dim3 grid((N_ * PLANE8_) / 256, 2);    // (14112, 2) — exact fit
    cutout_color_kernel<<<grid, block>>>(x, colors, tops, lefts, out);
}

// round 11
// speedup vs baseline: 1.0049x; 1.0049x over previous
#include <cuda_runtime.h>
#include <stdint.h>

// CutoutColor: out[n,c,h,w] = colors[n,c] if h in [top, top+28) && w in [left, left+28)
//              else x[n,c,h,w]
// x [4096, 9, 84, 84] f32, colors [4096, 9] f32, tops/lefts [4096] i32.
//
// FINAL (converged at the HBM mixed-stream ceiling, ~6.86 TB/s = 86% of spec):
//  - channel-fused: one thread = one spatial float4 across all 9 channels
//    (mask computed once, 9 front-batched independent LDG.128 -> MLP=9)
//  - patch-interior read-skip (fully-covered vectors never read x)
//  - .cs (evict-first) streaming hints on the bulk load/store streams
//  - flattened exact-fit 1D grid: 4096*1764 = 28,224 x 256, zero tail threads
// Experiments that did NOT move the needle (HBM bus is the binding limit):
// 8-sample/block fusion (regressed: occupancy/divergence), 256-bit v8.b32
// vectors (neutral: L1tex queue is per-line, not per-instruction).

#define N_     4096
#define C_     9
#define H_     84
#define W_     84
#define PATCH_ 28
#define W4_    (W_ / 4)      // 21
#define HW4_   (H_ * W4_)    // 1764
#define TOTAL_ (N_ * HW4_)   // 7,225,344 = 28224 * 256

__global__ __launch_bounds__(256)
void cutout_color_kernel(const float4* __restrict__ x,
                         const float*  __restrict__ colors,
                         const int*    __restrict__ tops,
                         const int*    __restrict__ lefts,
                         float4*       __restrict__ out)
{
    const int tid = blockIdx.x * blockDim.x + threadIdx.x;  // 0 .. TOTAL_-1, exact

    const int n = tid / HW4_;            // const-divisor -> mul/shift
    const int i = tid - n * HW4_;        // spatial vec idx 0..1763

    const int h  = i / W4_;              // const-divisor -> mul/shift
    const int w0 = (i - h * W4_) * 4;

    const int top  = tops[n];            // ~warp-uniform -> L1 broadcast
    const int left = lefts[n];

    const bool row_in = (h >= top) & (h < top + PATCH_);
    const int  lo = left, hi = left + PATCH_;

    // vec index of (n, c=0, i); channel stride HW4_. Max ~65.0M < 2^31.
    const int base = n * (C_ * HW4_) + i;

    const float* __restrict__ col = colors + n * C_;

    if (row_in & (w0 >= lo) & (w0 + 3 < hi)) {
        // whole vector inside the patch for every channel: pure writes
        #pragma unroll
        for (int c = 0; c < C_; ++c) {
            const float f = col[c];
            __stcs(&out[base + c * HW4_], make_float4(f, f, f, f));
        }
        return;
    }

    // Front-batch all 9 independent streaming loads (MLP=9), then select+store.
    float4 v[C_];
    #pragma unroll
    for (int c = 0; c < C_; ++c)
        v[c] = __ldcs(&x[base + c * HW4_]);

    if (row_in) {
        const bool m0 = (w0 + 0 >= lo) & (w0 + 0 < hi);
        const bool m1 = (w0 + 1 >= lo) & (w0 + 1 < hi);
        const bool m2 = (w0 + 2 >= lo) & (w0 + 2 < hi);
        const bool m3 = (w0 + 3 >= lo) & (w0 + 3 < hi);
        #pragma unroll
        for (int c = 0; c < C_; ++c) {
            const float f = col[c];
            if (m0) v[c].x = f;
            if (m1) v[c].y = f;
            if (m2) v[c].z = f;
            if (m3) v[c].w = f;
        }
    }

    #pragma unroll
    for (int c = 0; c < C_; ++c)
        __stcs(&out[base + c * HW4_], v[c]);
}

extern "C" void kernel_launch(void* const* d_in, const int* in_sizes, int n_in,
                              void* d_out, int out_size)
{
    const float4* x      = (const float4*)d_in[0];
    const float*  colors = (const float*) d_in[1];
    const int*    tops   = (const int*)   d_in[2];
    const int*    lefts  = (const int*)   d_in[3];
    float4*       out    = (float4*)      d_out;

    dim3 block(256);
    dim3 grid(TOTAL_ / 256);             // 28224 blocks, exact fit
    cutout_color_kernel<<<grid, block>>>(x, colors, tops, lefts, out);
}

// round 12
// speedup vs baseline: 1.0060x; 1.0011x over previous
#include <cuda_runtime.h>
#include <stdint.h>

// CutoutColor: out[n,c,h,w] = colors[n,c] if h in [top, top+28) && w in [left, left+28)
//              else x[n,c,h,w]
// x [4096, 9, 84, 84] f32, colors [4096, 9] f32, tops/lefts [4096] i32.
//
// FINAL (converged at the HBM mixed-stream ceiling, ~6.86 TB/s = 86% of spec):
//  - channel-fused: one thread = one spatial float4 across all 9 channels
//    (mask computed once, 9 front-batched independent LDG.128 -> MLP=9)
//  - patch-interior read-skip (fully-covered vectors never read x)
//  - .cs (evict-first) streaming hints on the bulk load/store streams
//  - flattened exact-fit 1D grid, 128-thread blocks: 46 regs x 128 thr lets
//    11 blocks/SM (44 warps, 68.75% theoretical occ) vs 5x256 (40 warps),
//    and 56,448 blocks drain more evenly in the final wave.
// Levers tested and rejected: 8-sample/block fusion (regressed), 256-bit
// v8.b32 (neutral: L1tex queue is per-line), memcpy+patch-paint (more traffic).

#define N_     4096
#define C_     9
#define H_     84
#define W_     84
#define PATCH_ 28
#define W4_    (W_ / 4)      // 21
#define HW4_   (H_ * W4_)    // 1764
#define TOTAL_ (N_ * HW4_)   // 7,225,344 = 56448 * 128

__global__ __launch_bounds__(128)
void cutout_color_kernel(const float4* __restrict__ x,
                         const float*  __restrict__ colors,
                         const int*    __restrict__ tops,
                         const int*    __restrict__ lefts,
                         float4*       __restrict__ out)
{
    const int tid = blockIdx.x * blockDim.x + threadIdx.x;  // 0 .. TOTAL_-1, exact

    const int n = tid / HW4_;            // const-divisor -> mul/shift
    const int i = tid - n * HW4_;        // spatial vec idx 0..1763

    const int h  = i / W4_;              // const-divisor -> mul/shift
    const int w0 = (i - h * W4_) * 4;

    const int top  = tops[n];            // ~warp-uniform -> L1 broadcast
    const int left = lefts[n];

    const bool row_in = (h >= top) & (h < top + PATCH_);
    const int  lo = left, hi = left + PATCH_;

    // vec index of (n, c=0, i); channel stride HW4_. Max ~65.0M < 2^31.
    const int base = n * (C_ * HW4_) + i;

    const float* __restrict__ col = colors + n * C_;

    if (row_in & (w0 >= lo) & (w0 + 3 < hi)) {
        // whole vector inside the patch for every channel: pure writes
        #pragma unroll
        for (int c = 0; c < C_; ++c) {
            const float f = col[c];
            __stcs(&out[base + c * HW4_], make_float4(f, f, f, f));
        }
        return;
    }

    // Front-batch all 9 independent streaming loads (MLP=9), then select+store.
    float4 v[C_];
    #pragma unroll
    for (int c = 0; c < C_; ++c)
        v[c] = __ldcs(&x[base + c * HW4_]);

    if (row_in) {
        const bool m0 = (w0 + 0 >= lo) & (w0 + 0 < hi);
        const bool m1 = (w0 + 1 >= lo) & (w0 + 1 < hi);
        const bool m2 = (w0 + 2 >= lo) & (w0 + 2 < hi);
        const bool m3 = (w0 + 3 >= lo) & (w0 + 3 < hi);
        #pragma unroll
        for (int c = 0; c < C_; ++c) {
            const float f = col[c];
            if (m0) v[c].x = f;
            if (m1) v[c].y = f;
            if (m2) v[c].z = f;
            if (m3) v[c].w = f;
        }
    }

    #pragma unroll
    for (int c = 0; c < C_; ++c)
        __stcs(&out[base + c * HW4_], v[c]);
}

extern "C" void kernel_launch(void* const* d_in, const int* in_sizes, int n_in,
                              void* d_out, int out_size)
{
    const float4* x      = (const float4*)d_in[0];
    const float*  colors = (const float*) d_in[1];
    const int*    tops   = (const int*)   d_in[2];
    const int*    lefts  = (const int*)   d_in[3];
    float4*       out    = (float4*)      d_out;

    dim3 block(128);
    dim3 grid(TOTAL_ / 128);             // 56448 blocks, exact fit
    cutout_color_kernel<<<grid, block>>>(x, colors, tops, lefts, out);
}